// round 1
// baseline (speedup 1.0000x reference)
#include <cuda_runtime.h>

#define B_  4
#define TQ  512
#define TK  512
#define QD  1024
#define CD  256

// Scratch for projected tensors, stored TRANSPOSED: [b][c][row]  (C-major)
__device__ float g_q2t[B_ * CD * TQ];   // (b*256 + c)*512 + q
__device__ float g_k2t[B_ * CD * TK];   // (b*256 + c)*512 + k

__device__ __forceinline__ float tanh_fast(float x) {
    float y;
    asm("tanh.approx.f32 %0, %1;" : "=f"(y) : "f"(x));
    return y;
}

// ---------------------------------------------------------------------------
// Projection GEMM: Out^T[b][n][row] = sum_k X[b][row][k] * W[k][n]
// M = B_*T = 2048 (rows), Kdim = 1024, N = 256.
// Block tile 64x64, BK=16, 256 threads, 4x4 per-thread microtile.
// blockIdx.z selects (query,Wq)->g_q2t vs (key,Wk)->g_k2t.
// ---------------------------------------------------------------------------
__global__ __launch_bounds__(256) void proj_kernel(
    const float* __restrict__ Xq, const float* __restrict__ Xk,
    const float* __restrict__ Wqm, const float* __restrict__ Wkm)
{
    const float* X;
    const float* W;
    float* OutT;
    if (blockIdx.z == 0) { X = Xq; W = Wqm; OutT = g_q2t; }
    else                 { X = Xk; W = Wkm; OutT = g_k2t; }

    const int m0 = blockIdx.y * 64;   // row tile (within flattened b*T)
    const int n0 = blockIdx.x * 64;   // c tile

    __shared__ float As[16][64];      // [k][m]
    __shared__ float Bs[16][64];      // [k][n]

    const int t  = threadIdx.x;
    const int ty = t >> 4;            // 0..15
    const int tx = t & 15;            // 0..15

    // load indexing
    const int am = t >> 2;            // 0..63
    const int ak = (t & 3) << 2;      // 0,4,8,12
    const int bk = t >> 4;            // 0..15
    const int bn = (t & 15) << 2;     // 0..60

    float acc[4][4] = {};

    for (int k0 = 0; k0 < QD; k0 += 16) {
        float4 av = *(const float4*)&X[(size_t)(m0 + am) * QD + k0 + ak];
        float4 bv = *(const float4*)&W[(size_t)(k0 + bk) * CD + n0 + bn];
        As[ak + 0][am] = av.x;
        As[ak + 1][am] = av.y;
        As[ak + 2][am] = av.z;
        As[ak + 3][am] = av.w;
        *(float4*)&Bs[bk][bn] = bv;
        __syncthreads();

        #pragma unroll
        for (int kk = 0; kk < 16; kk++) {
            float4 a = *(const float4*)&As[kk][ty << 2];
            float4 b = *(const float4*)&Bs[kk][tx << 2];
            acc[0][0] += a.x * b.x; acc[0][1] += a.x * b.y; acc[0][2] += a.x * b.z; acc[0][3] += a.x * b.w;
            acc[1][0] += a.y * b.x; acc[1][1] += a.y * b.y; acc[1][2] += a.y * b.z; acc[1][3] += a.y * b.w;
            acc[2][0] += a.z * b.x; acc[2][1] += a.z * b.y; acc[2][2] += a.z * b.z; acc[2][3] += a.z * b.w;
            acc[3][0] += a.w * b.x; acc[3][1] += a.w * b.y; acc[3][2] += a.w * b.z; acc[3][3] += a.w * b.w;
        }
        __syncthreads();
    }

    // Transposed epilogue: OutT[(b*CD + n) * T + row], float4 along row.
    const int b  = m0 >> 9;                 // 512 rows per batch, tiles never straddle
    const int qb = (m0 & 511) + (ty << 2);  // row within batch (multiple of 4)
    #pragma unroll
    for (int j = 0; j < 4; j++) {
        const int n = n0 + (tx << 2) + j;
        float4 v = make_float4(acc[0][j], acc[1][j], acc[2][j], acc[3][j]);
        *(float4*)&OutT[((size_t)b * CD + n) * TQ + qb] = v;
    }
}

// ---------------------------------------------------------------------------
// Score kernel: out[b,q,k] = b_attn + sum_c w[c]*tanh(q2[b,q,c]+k2[b,k,c])
// Block: 32x32 (q x k) output tile, 256 threads = (ty 0..7) x (tx 0..31).
// Thread -> q rows {ty, ty+8, ty+16, ty+24}, k col tx.  C chunked by 64.
// SMEM tiles are C-major: k_s[c][tx] coalesced, q_s[c][qrow] broadcast.
// ---------------------------------------------------------------------------
__global__ __launch_bounds__(256) void score_kernel(
    const float* __restrict__ w_attn, const float* __restrict__ b_attn,
    float* __restrict__ out)
{
    const int b  = blockIdx.z;
    const int q0 = blockIdx.y * 32;
    const int k0 = blockIdx.x * 32;

    __shared__ float q_s[64][32];
    __shared__ float k_s[64][32];
    __shared__ float w_s[CD];

    const int t  = threadIdx.x;
    const int ty = t >> 5;    // 0..7
    const int tx = t & 31;    // 0..31

    w_s[t] = w_attn[t];       // t in [0,256) == CD

    const float* qbase = g_q2t + (size_t)b * CD * TQ + q0;
    const float* kbase = g_k2t + (size_t)b * CD * TK + k0;

    float acc0 = 0.f, acc1 = 0.f, acc2 = 0.f, acc3 = 0.f;

    for (int c0 = 0; c0 < CD; c0 += 64) {
        __syncthreads();
        #pragma unroll
        for (int r = 0; r < 2; r++) {
            const int v    = t + r * 256;     // 0..511
            const int row  = v >> 3;          // 0..63 (c within chunk)
            const int col4 = (v & 7) << 2;    // 0..28
            *(float4*)&q_s[row][col4] =
                *(const float4*)&qbase[(size_t)(c0 + row) * TQ + col4];
            *(float4*)&k_s[row][col4] =
                *(const float4*)&kbase[(size_t)(c0 + row) * TK + col4];
        }
        __syncthreads();

        #pragma unroll 8
        for (int c = 0; c < 64; c++) {
            const float kv = k_s[c][tx];
            const float w  = w_s[c0 + c];
            acc0 += w * tanh_fast(q_s[c][ty     ] + kv);
            acc1 += w * tanh_fast(q_s[c][ty +  8] + kv);
            acc2 += w * tanh_fast(q_s[c][ty + 16] + kv);
            acc3 += w * tanh_fast(q_s[c][ty + 24] + kv);
        }
    }

    const float bias = b_attn[0];
    const size_t obase = ((size_t)b * TQ + q0) * TK + k0 + tx;
    out[obase + (size_t)(ty     ) * TK] = acc0 + bias;
    out[obase + (size_t)(ty +  8) * TK] = acc1 + bias;
    out[obase + (size_t)(ty + 16) * TK] = acc2 + bias;
    out[obase + (size_t)(ty + 24) * TK] = acc3 + bias;
}

extern "C" void kernel_launch(void* const* d_in, const int* in_sizes, int n_in,
                              void* d_out, int out_size)
{
    const float* query  = (const float*)d_in[0];
    const float* key    = (const float*)d_in[1];
    const float* Wq     = (const float*)d_in[2];
    const float* Wk     = (const float*)d_in[3];
    const float* w_attn = (const float*)d_in[4];
    const float* b_attn = (const float*)d_in[5];
    float* out = (float*)d_out;

    dim3 pg(CD / 64, (B_ * TQ) / 64, 2);   // (4, 32, 2)
    proj_kernel<<<pg, 256>>>(query, key, Wq, Wk);

    dim3 sg(TK / 32, TQ / 32, B_);         // (16, 16, 4)
    score_kernel<<<sg, 256>>>(w_attn, b_attn, out);
}

// round 3
// speedup vs baseline: 1.5186x; 1.5186x over previous
#include <cuda_runtime.h>
#include <cstdint>

#define B_  4
#define TQ  512
#define TK  512
#define QD  1024
#define CD  256

// Scratch: projected tensors TRANSPOSED [b][c][row] (C-major), plus W^T copies.
__device__ float g_q2t[B_ * CD * TQ];
__device__ float g_k2t[B_ * CD * TK];
__device__ float g_wqt[CD * QD];     // Wq^T: [n][k]
__device__ float g_wkt[CD * QD];     // Wk^T: [n][k]

__device__ __forceinline__ uint32_t smem_u32(const void* p) {
    uint32_t a;
    asm("{ .reg .u64 t; cvta.to.shared.u64 t, %1; cvt.u32.u64 %0, t; }"
        : "=r"(a) : "l"(p));
    return a;
}
__device__ __forceinline__ void cp_async16(uint32_t saddr, const void* g) {
    asm volatile("cp.async.cg.shared.global [%0], [%1], 16;" :: "r"(saddr), "l"(g));
}
__device__ __forceinline__ void cp_commit() {
    asm volatile("cp.async.commit_group;" ::: "memory");
}
__device__ __forceinline__ void cp_wait1() {
    asm volatile("cp.async.wait_group 1;" ::: "memory");
}
__device__ __forceinline__ void cp_wait0() {
    asm volatile("cp.async.wait_group 0;" ::: "memory");
}
__device__ __forceinline__ void mma_tf32(float* d, const uint32_t* a, const uint32_t* b) {
    asm volatile(
        "mma.sync.aligned.m16n8k8.row.col.f32.tf32.tf32.f32 "
        "{%0,%1,%2,%3}, {%4,%5,%6,%7}, {%8,%9}, {%0,%1,%2,%3};\n"
        : "+f"(d[0]), "+f"(d[1]), "+f"(d[2]), "+f"(d[3])
        : "r"(a[0]), "r"(a[1]), "r"(a[2]), "r"(a[3]), "r"(b[0]), "r"(b[1]));
}
__device__ __forceinline__ float tanh_fast(float x) {
    float y;
    asm("tanh.approx.f32 %0, %1;" : "=f"(y) : "f"(x));
    return y;
}

// ---------------------------------------------------------------------------
// Transpose W [K=1024, N=256] -> Wt [N=256, K=1024]. z: 0=Wq, 1=Wk.
// ---------------------------------------------------------------------------
__global__ __launch_bounds__(256) void transpose_w(
    const float* __restrict__ Wq, const float* __restrict__ Wk)
{
    __shared__ float tile[32][33];
    const float* W  = blockIdx.z ? Wk : Wq;
    float*       Wt = blockIdx.z ? g_wkt : g_wqt;
    const int k0 = blockIdx.x * 32;
    const int n0 = blockIdx.y * 32;
    const int tx = threadIdx.x & 31, ty = threadIdx.x >> 5;  // 32 x 8
    #pragma unroll
    for (int r = 0; r < 32; r += 8)
        tile[ty + r][tx] = W[(size_t)(k0 + ty + r) * CD + n0 + tx];
    __syncthreads();
    #pragma unroll
    for (int r = 0; r < 32; r += 8)
        Wt[(size_t)(n0 + ty + r) * QD + k0 + tx] = tile[tx][ty + r];
}

// ---------------------------------------------------------------------------
// Projection via mma.sync tf32 (family-portable HMMA path).
// C[m][n] = sum_k X[m][k] * Wt[n][k],  m in row tile of 128, n tile of 64.
// Stored transposed (C-major) for the score kernel.
// 8 warps as 4(M) x 2(N); warp tile 32x32; mma m16n8k8; BK=32; cp.async x2 buf.
// SMEM row stride 36 floats -> conflict-free fragment LDS (banks = 4i + c).
// ---------------------------------------------------------------------------
#define BM     128
#define BN     64
#define BK     32
#define LDS_S  36                       // smem row stride in floats
#define A_FL   (BM * LDS_S)             // 4608 floats
#define B_FL   (BN * LDS_S)             // 2304 floats
#define NITER  (QD / BK)                // 32
#define STG_LD 132                      // epilogue staging stride [n][m]
#define DYN_SMEM ((2 * A_FL + 2 * B_FL) * 4)   // 55296 B (stage reuses A region)

__global__ __launch_bounds__(256) void proj_mma_kernel(
    const float* __restrict__ Xq, const float* __restrict__ Xk)
{
    extern __shared__ float sm[];
    float* Abuf[2] = { sm,            sm + A_FL };
    float* Bbuf[2] = { sm + 2 * A_FL, sm + 2 * A_FL + B_FL };
    const uint32_t smb = smem_u32(sm);
    const uint32_t a_u[2] = { smb,                (uint32_t)(smb + A_FL * 4) };
    const uint32_t b_u[2] = { smb + 2 * A_FL * 4, (uint32_t)(smb + (2 * A_FL + B_FL) * 4) };

    const int t    = threadIdx.x;
    const int lane = t & 31;
    const int wid  = t >> 5;
    const int wm   = wid & 3;           // 0..3 : 32-row slice
    const int wn   = wid >> 2;          // 0..1 : 32-col slice
    const int r    = lane >> 2;         // 0..7
    const int c    = lane & 3;          // 0..3

    const float* X    = blockIdx.z ? Xk : Xq;
    const float* Wt   = blockIdx.z ? g_wkt : g_wqt;
    float*       OutT = blockIdx.z ? g_k2t : g_q2t;

    const int m0 = blockIdx.x * BM;     // row tile in flattened (b*T)
    const int n0 = blockIdx.y * BN;     // c tile

    const float* Xb = X + (size_t)m0 * QD;
    const float* Wb = Wt + (size_t)n0 * QD;

    // per-thread cp.async coords
    const int arow = t >> 3;            // 0..31 (+32 per iter), row within tile
    const int aj   = t & 7;             // 16B chunk within 32-float k-slice

    float acc[2][4][4] = {};

    // ---- prologue: tile 0 ----
    {
        #pragma unroll
        for (int it = 0; it < 4; it++) {
            const int row = arow + it * 32;
            cp_async16(a_u[0] + (uint32_t)(row * LDS_S + aj * 4) * 4,
                       Xb + (size_t)row * QD + aj * 4);
        }
        #pragma unroll
        for (int it = 0; it < 2; it++) {
            const int row = arow + it * 32;
            cp_async16(b_u[0] + (uint32_t)(row * LDS_S + aj * 4) * 4,
                       Wb + (size_t)row * QD + aj * 4);
        }
        cp_commit();
    }

    for (int i = 0; i < NITER; i++) {
        if (i + 1 < NITER) {
            const int nb = (i + 1) & 1;
            const int kf = (i + 1) * BK;
            #pragma unroll
            for (int it = 0; it < 4; it++) {
                const int row = arow + it * 32;
                cp_async16(a_u[nb] + (uint32_t)(row * LDS_S + aj * 4) * 4,
                           Xb + (size_t)row * QD + kf + aj * 4);
            }
            #pragma unroll
            for (int it = 0; it < 2; it++) {
                const int row = arow + it * 32;
                cp_async16(b_u[nb] + (uint32_t)(row * LDS_S + aj * 4) * 4,
                           Wb + (size_t)row * QD + kf + aj * 4);
            }
        }
        cp_commit();
        if (i + 1 < NITER) cp_wait1(); else cp_wait0();
        __syncthreads();

        const float* As = Abuf[i & 1];
        const float* Bs = Bbuf[i & 1];

        #pragma unroll
        for (int kfi = 0; kfi < 4; kfi++) {
            const int kf = kfi * 8;
            uint32_t af[2][4], bf[4][2];
            #pragma unroll
            for (int mt = 0; mt < 2; mt++) {
                const int m = wm * 32 + mt * 16 + r;
                af[mt][0] = __float_as_uint(As[(m    ) * LDS_S + kf + c    ]);
                af[mt][1] = __float_as_uint(As[(m + 8) * LDS_S + kf + c    ]);
                af[mt][2] = __float_as_uint(As[(m    ) * LDS_S + kf + c + 4]);
                af[mt][3] = __float_as_uint(As[(m + 8) * LDS_S + kf + c + 4]);
            }
            #pragma unroll
            for (int nt = 0; nt < 4; nt++) {
                const int n = wn * 32 + nt * 8 + r;
                bf[nt][0] = __float_as_uint(Bs[n * LDS_S + kf + c    ]);
                bf[nt][1] = __float_as_uint(Bs[n * LDS_S + kf + c + 4]);
            }
            #pragma unroll
            for (int mt = 0; mt < 2; mt++)
                #pragma unroll
                for (int nt = 0; nt < 4; nt++)
                    mma_tf32(acc[mt][nt], af[mt], bf[nt]);
        }
        __syncthreads();
    }

    // ---- epilogue: stage transposed [n][m] in smem, store C-major float4 ----
    float* stg = sm;                    // reuse; 64 * 132 = 8448 floats
    #pragma unroll
    for (int mt = 0; mt < 2; mt++) {
        const int mlo = wm * 32 + mt * 16 + r;
        #pragma unroll
        for (int nt = 0; nt < 4; nt++) {
            const int n = wn * 32 + nt * 8 + 2 * c;
            stg[(n    ) * STG_LD + mlo    ] = acc[mt][nt][0];
            stg[(n + 1) * STG_LD + mlo    ] = acc[mt][nt][1];
            stg[(n    ) * STG_LD + mlo + 8] = acc[mt][nt][2];
            stg[(n + 1) * STG_LD + mlo + 8] = acc[mt][nt][3];
        }
    }
    __syncthreads();

    const int b_idx = m0 >> 9;          // batch (tiles never straddle: 128 | 512)
    const int m_ib  = m0 & 511;         // row base within batch
    #pragma unroll
    for (int it = 0; it < 8; it++) {
        const int idx = t + it * 256;   // 0..2047 float4 chunks
        const int n   = idx >> 5;       // 0..63
        const int mj  = idx & 31;       // float4 index along m (0..31)
        float4 v = *(const float4*)&stg[n * STG_LD + mj * 4];
        *(float4*)&OutT[((size_t)b_idx * CD + n0 + n) * TQ + m_ib + mj * 4] = v;
    }
}

// ---------------------------------------------------------------------------
// Score kernel (unchanged): out[b,q,k] = b + sum_c w[c]*tanh(q2+k2). MUFU-bound.
// ---------------------------------------------------------------------------
__global__ __launch_bounds__(256) void score_kernel(
    const float* __restrict__ w_attn, const float* __restrict__ b_attn,
    float* __restrict__ out)
{
    const int b  = blockIdx.z;
    const int q0 = blockIdx.y * 32;
    const int k0 = blockIdx.x * 32;

    __shared__ float q_s[64][32];
    __shared__ float k_s[64][32];
    __shared__ float w_s[CD];

    const int t  = threadIdx.x;
    const int ty = t >> 5;
    const int tx = t & 31;

    w_s[t] = w_attn[t];

    const float* qbase = g_q2t + (size_t)b * CD * TQ + q0;
    const float* kbase = g_k2t + (size_t)b * CD * TK + k0;

    float acc0 = 0.f, acc1 = 0.f, acc2 = 0.f, acc3 = 0.f;

    for (int c0 = 0; c0 < CD; c0 += 64) {
        __syncthreads();
        #pragma unroll
        for (int rr = 0; rr < 2; rr++) {
            const int v    = t + rr * 256;
            const int row  = v >> 3;
            const int col4 = (v & 7) << 2;
            *(float4*)&q_s[row][col4] =
                *(const float4*)&qbase[(size_t)(c0 + row) * TQ + col4];
            *(float4*)&k_s[row][col4] =
                *(const float4*)&kbase[(size_t)(c0 + row) * TK + col4];
        }
        __syncthreads();

        #pragma unroll 8
        for (int cc = 0; cc < 64; cc++) {
            const float kv = k_s[cc][tx];
            const float w  = w_s[c0 + cc];
            acc0 += w * tanh_fast(q_s[cc][ty     ] + kv);
            acc1 += w * tanh_fast(q_s[cc][ty +  8] + kv);
            acc2 += w * tanh_fast(q_s[cc][ty + 16] + kv);
            acc3 += w * tanh_fast(q_s[cc][ty + 24] + kv);
        }
    }

    const float bias = b_attn[0];
    const size_t obase = ((size_t)b * TQ + q0) * TK + k0 + tx;
    out[obase + (size_t)(ty     ) * TK] = acc0 + bias;
    out[obase + (size_t)(ty +  8) * TK] = acc1 + bias;
    out[obase + (size_t)(ty + 16) * TK] = acc2 + bias;
    out[obase + (size_t)(ty + 24) * TK] = acc3 + bias;
}

extern "C" void kernel_launch(void* const* d_in, const int* in_sizes, int n_in,
                              void* d_out, int out_size)
{
    const float* query  = (const float*)d_in[0];
    const float* key    = (const float*)d_in[1];
    const float* Wq     = (const float*)d_in[2];
    const float* Wk     = (const float*)d_in[3];
    const float* w_attn = (const float*)d_in[4];
    const float* b_attn = (const float*)d_in[5];
    float* out = (float*)d_out;

    cudaFuncSetAttribute(proj_mma_kernel,
                         cudaFuncAttributeMaxDynamicSharedMemorySize, DYN_SMEM);

    dim3 tg(QD / 32, CD / 32, 2);              // (32, 8, 2)
    transpose_w<<<tg, 256>>>(Wq, Wk);

    dim3 pg((B_ * TQ) / BM, CD / BN, 2);       // (16, 4, 2) = 128 CTAs
    proj_mma_kernel<<<pg, 256, DYN_SMEM>>>(query, key);

    dim3 sg(TK / 32, TQ / 32, B_);             // (16, 16, 4)
    score_kernel<<<sg, 256>>>(w_attn, b_attn, out);
}

// round 4
// speedup vs baseline: 1.5196x; 1.0007x over previous
#include <cuda_runtime.h>
#include <cuda_fp16.h>
#include <cstdint>

#define B_  4
#define TQ  512
#define TK  512
#define QD  1024
#define CD  256

// Scratch: projected tensors TRANSPOSED [b][c][row] (C-major), plus W^T copies.
__device__ float g_q2t[B_ * CD * TQ];
__device__ float g_k2t[B_ * CD * TK];
__device__ float g_wqt[CD * QD];     // Wq^T: [n][k], pre-rounded to tf32-RN
__device__ float g_wkt[CD * QD];

__device__ __forceinline__ uint32_t smem_u32(const void* p) {
    uint32_t a;
    asm("{ .reg .u64 t; cvta.to.shared.u64 t, %1; cvt.u32.u64 %0, t; }"
        : "=r"(a) : "l"(p));
    return a;
}
__device__ __forceinline__ void cp_async16(uint32_t saddr, const void* g) {
    asm volatile("cp.async.cg.shared.global [%0], [%1], 16;" :: "r"(saddr), "l"(g));
}
__device__ __forceinline__ void cp_commit() {
    asm volatile("cp.async.commit_group;" ::: "memory");
}
__device__ __forceinline__ void cp_wait1() {
    asm volatile("cp.async.wait_group 1;" ::: "memory");
}
__device__ __forceinline__ void cp_wait0() {
    asm volatile("cp.async.wait_group 0;" ::: "memory");
}
__device__ __forceinline__ void mma_tf32(float* d, const uint32_t* a, const uint32_t* b) {
    asm volatile(
        "mma.sync.aligned.m16n8k8.row.col.f32.tf32.tf32.f32 "
        "{%0,%1,%2,%3}, {%4,%5,%6,%7}, {%8,%9}, {%0,%1,%2,%3};\n"
        : "+f"(d[0]), "+f"(d[1]), "+f"(d[2]), "+f"(d[3])
        : "r"(a[0]), "r"(a[1]), "r"(a[2]), "r"(a[3]), "r"(b[0]), "r"(b[1]));
}
__device__ __forceinline__ uint32_t tanh_h2(uint32_t x) {
    uint32_t y;
    asm("tanh.approx.f16x2 %0, %1;" : "=r"(y) : "r"(x));
    return y;
}
// Round fp32 bit pattern so tf32 truncation (drop 13 bits) becomes round-to-nearest.
#define TF32_RN(u) ((u) + 0x1000u)

// ---------------------------------------------------------------------------
// Transpose W [K=1024, N=256] -> Wt [N=256, K=1024], pre-rounded to tf32-RN.
// ---------------------------------------------------------------------------
__global__ __launch_bounds__(256) void transpose_w(
    const float* __restrict__ Wq, const float* __restrict__ Wk)
{
    __shared__ float tile[32][33];
    const float* W  = blockIdx.z ? Wk : Wq;
    float*       Wt = blockIdx.z ? g_wkt : g_wqt;
    const int k0 = blockIdx.x * 32;
    const int n0 = blockIdx.y * 32;
    const int tx = threadIdx.x & 31, ty = threadIdx.x >> 5;  // 32 x 8
    #pragma unroll
    for (int r = 0; r < 32; r += 8) {
        uint32_t u = __float_as_uint(W[(size_t)(k0 + ty + r) * CD + n0 + tx]);
        tile[ty + r][tx] = __uint_as_float(TF32_RN(u));
    }
    __syncthreads();
    #pragma unroll
    for (int r = 0; r < 32; r += 8)
        Wt[(size_t)(n0 + ty + r) * QD + k0 + tx] = tile[tx][ty + r];
}

// ---------------------------------------------------------------------------
// Projection via mma.sync tf32. 3-stage cp.async pipeline, 1 sync/iter.
// C[m][n] = sum_k X[m][k]*Wt[n][k]; output stored C-major transposed.
// 8 warps = 4(M) x 2(N), warp tile 32x32, BK=32.
// ---------------------------------------------------------------------------
#define BM     128
#define BN     64
#define BK     32
#define LDS_S  36
#define A_FL   (BM * LDS_S)             // 4608 floats
#define B_FL   (BN * LDS_S)             // 2304 floats
#define NITER  (QD / BK)                // 32
#define STG_LD 132
#define STAGES 3
#define DYN_SMEM (STAGES * (A_FL + B_FL) * 4)   // 82944 B

__global__ __launch_bounds__(256) void proj_mma_kernel(
    const float* __restrict__ Xq, const float* __restrict__ Xk)
{
    extern __shared__ float sm[];
    const uint32_t smb = smem_u32(sm);

    float*   Abuf[STAGES];
    float*   Bbuf[STAGES];
    uint32_t a_u[STAGES], b_u[STAGES];
    #pragma unroll
    for (int s = 0; s < STAGES; s++) {
        Abuf[s] = sm + s * (A_FL + B_FL);
        Bbuf[s] = Abuf[s] + A_FL;
        a_u[s]  = smb + (uint32_t)(s * (A_FL + B_FL)) * 4u;
        b_u[s]  = a_u[s] + A_FL * 4u;
    }

    const int t    = threadIdx.x;
    const int lane = t & 31;
    const int wid  = t >> 5;
    const int wm   = wid & 3;
    const int wn   = wid >> 2;
    const int r    = lane >> 2;
    const int c    = lane & 3;

    const float* X    = blockIdx.z ? Xk : Xq;
    const float* Wt   = blockIdx.z ? g_wkt : g_wqt;
    float*       OutT = blockIdx.z ? g_k2t : g_q2t;

    const int m0 = blockIdx.x * BM;
    const int n0 = blockIdx.y * BN;

    const float* Xb = X  + (size_t)m0 * QD;
    const float* Wb = Wt + (size_t)n0 * QD;

    const int arow = t >> 3;
    const int aj   = t & 7;

    float acc[2][4][4] = {};

    // ---- prologue: tiles 0 and 1 ----
    #pragma unroll
    for (int p = 0; p < 2; p++) {
        const int kf = p * BK;
        #pragma unroll
        for (int it = 0; it < 4; it++) {
            const int row = arow + it * 32;
            cp_async16(a_u[p] + (uint32_t)(row * LDS_S + aj * 4) * 4,
                       Xb + (size_t)row * QD + kf + aj * 4);
        }
        #pragma unroll
        for (int it = 0; it < 2; it++) {
            const int row = arow + it * 32;
            cp_async16(b_u[p] + (uint32_t)(row * LDS_S + aj * 4) * 4,
                       Wb + (size_t)row * QD + kf + aj * 4);
        }
        cp_commit();
    }

    for (int i = 0; i < NITER; i++) {
        if (i + 1 < NITER) cp_wait1(); else cp_wait0();
        __syncthreads();

        const int sb = i % STAGES;
        const float* As = Abuf[sb];
        const float* Bs = Bbuf[sb];

        #pragma unroll
        for (int kfi = 0; kfi < 4; kfi++) {
            const int kf = kfi * 8;
            uint32_t af[2][4], bf[4][2];
            #pragma unroll
            for (int mt = 0; mt < 2; mt++) {
                const int m = wm * 32 + mt * 16 + r;
                af[mt][0] = TF32_RN(__float_as_uint(As[(m    ) * LDS_S + kf + c    ]));
                af[mt][1] = TF32_RN(__float_as_uint(As[(m + 8) * LDS_S + kf + c    ]));
                af[mt][2] = TF32_RN(__float_as_uint(As[(m    ) * LDS_S + kf + c + 4]));
                af[mt][3] = TF32_RN(__float_as_uint(As[(m + 8) * LDS_S + kf + c + 4]));
            }
            #pragma unroll
            for (int nt = 0; nt < 4; nt++) {
                const int n = wn * 32 + nt * 8 + r;
                bf[nt][0] = __float_as_uint(Bs[n * LDS_S + kf + c    ]);
                bf[nt][1] = __float_as_uint(Bs[n * LDS_S + kf + c + 4]);
            }
            #pragma unroll
            for (int mt = 0; mt < 2; mt++)
                #pragma unroll
                for (int nt = 0; nt < 4; nt++)
                    mma_tf32(acc[mt][nt], af[mt], bf[nt]);
        }

        // prefetch tile i+2 into stage (i+2)%STAGES
        if (i + 2 < NITER) {
            const int nb = (i + 2) % STAGES;
            const int kf = (i + 2) * BK;
            #pragma unroll
            for (int it = 0; it < 4; it++) {
                const int row = arow + it * 32;
                cp_async16(a_u[nb] + (uint32_t)(row * LDS_S + aj * 4) * 4,
                           Xb + (size_t)row * QD + kf + aj * 4);
            }
            #pragma unroll
            for (int it = 0; it < 2; it++) {
                const int row = arow + it * 32;
                cp_async16(b_u[nb] + (uint32_t)(row * LDS_S + aj * 4) * 4,
                           Wb + (size_t)row * QD + kf + aj * 4);
            }
        }
        cp_commit();
    }

    __syncthreads();

    // ---- epilogue: stage transposed [n][m], store C-major float4 ----
    float* stg = sm;                    // 64*132 = 8448 floats < smem
    #pragma unroll
    for (int mt = 0; mt < 2; mt++) {
        const int mlo = wm * 32 + mt * 16 + r;
        #pragma unroll
        for (int nt = 0; nt < 4; nt++) {
            const int n = wn * 32 + nt * 8 + 2 * c;
            stg[(n    ) * STG_LD + mlo    ] = acc[mt][nt][0];
            stg[(n + 1) * STG_LD + mlo    ] = acc[mt][nt][1];
            stg[(n    ) * STG_LD + mlo + 8] = acc[mt][nt][2];
            stg[(n + 1) * STG_LD + mlo + 8] = acc[mt][nt][3];
        }
    }
    __syncthreads();

    const int b_idx = m0 >> 9;
    const int m_ib  = m0 & 511;
    #pragma unroll
    for (int it = 0; it < 8; it++) {
        const int idx = t + it * 256;
        const int n   = idx >> 5;
        const int mj  = idx & 31;
        float4 v = *(const float4*)&stg[n * STG_LD + mj * 4];
        *(float4*)&OutT[((size_t)b_idx * CD + n0 + n) * TQ + m_ib + mj * 4] = v;
    }
}

// ---------------------------------------------------------------------------
// Score kernel, f16x2 tanh: 2 tanh per MUFU op, fp32 accumulation.
// ---------------------------------------------------------------------------
__global__ __launch_bounds__(256) void score_kernel(
    const float* __restrict__ w_attn, const float* __restrict__ b_attn,
    float* __restrict__ out)
{
    const int b  = blockIdx.z;
    const int q0 = blockIdx.y * 32;
    const int k0 = blockIdx.x * 32;

    __shared__ __half2 q_s2[32][32];   // [cpair][q col]
    __shared__ __half2 k_s2[32][32];   // [cpair][k col]
    __shared__ float   w_s[CD];

    const int t  = threadIdx.x;
    const int ty = t >> 5;    // 0..7
    const int tx = t & 31;    // 0..31

    w_s[t] = w_attn[t];

    const float* qbase = g_q2t + (size_t)b * CD * TQ + q0;
    const float* kbase = g_k2t + (size_t)b * CD * TK + k0;

    float acc0 = 0.f, acc1 = 0.f, acc2 = 0.f, acc3 = 0.f;

    for (int c0 = 0; c0 < CD; c0 += 64) {
        __syncthreads();
        {   // load + convert: thread -> (cpair, 4 cols) for q and k
            const int cp   = t >> 3;          // 0..31
            const int col4 = (t & 7) << 2;    // 0..28
            const size_t r0 = (size_t)(c0 + 2 * cp) * TQ + col4;
            float4 a0 = *(const float4*)&qbase[r0];
            float4 a1 = *(const float4*)&qbase[r0 + TQ];
            q_s2[cp][col4 + 0] = __floats2half2_rn(a0.x, a1.x);
            q_s2[cp][col4 + 1] = __floats2half2_rn(a0.y, a1.y);
            q_s2[cp][col4 + 2] = __floats2half2_rn(a0.z, a1.z);
            q_s2[cp][col4 + 3] = __floats2half2_rn(a0.w, a1.w);
            float4 c4 = *(const float4*)&kbase[r0];
            float4 c5 = *(const float4*)&kbase[r0 + TK];
            k_s2[cp][col4 + 0] = __floats2half2_rn(c4.x, c5.x);
            k_s2[cp][col4 + 1] = __floats2half2_rn(c4.y, c5.y);
            k_s2[cp][col4 + 2] = __floats2half2_rn(c4.z, c5.z);
            k_s2[cp][col4 + 3] = __floats2half2_rn(c4.w, c5.w);
        }
        __syncthreads();

        #pragma unroll 8
        for (int cp = 0; cp < 32; cp++) {
            const __half2 kh = k_s2[cp][tx];
            const float w0 = w_s[c0 + 2 * cp];
            const float w1 = w_s[c0 + 2 * cp + 1];

            {   __half2 a = __hadd2(q_s2[cp][ty], kh);
                uint32_t th = tanh_h2(*(uint32_t*)&a);
                float2 tf = __half22float2(*(__half2*)&th);
                acc0 = fmaf(w0, tf.x, acc0); acc0 = fmaf(w1, tf.y, acc0); }
            {   __half2 a = __hadd2(q_s2[cp][ty + 8], kh);
                uint32_t th = tanh_h2(*(uint32_t*)&a);
                float2 tf = __half22float2(*(__half2*)&th);
                acc1 = fmaf(w0, tf.x, acc1); acc1 = fmaf(w1, tf.y, acc1); }
            {   __half2 a = __hadd2(q_s2[cp][ty + 16], kh);
                uint32_t th = tanh_h2(*(uint32_t*)&a);
                float2 tf = __half22float2(*(__half2*)&th);
                acc2 = fmaf(w0, tf.x, acc2); acc2 = fmaf(w1, tf.y, acc2); }
            {   __half2 a = __hadd2(q_s2[cp][ty + 24], kh);
                uint32_t th = tanh_h2(*(uint32_t*)&a);
                float2 tf = __half22float2(*(__half2*)&th);
                acc3 = fmaf(w0, tf.x, acc3); acc3 = fmaf(w1, tf.y, acc3); }
        }
    }

    const float bias = b_attn[0];
    const size_t obase = ((size_t)b * TQ + q0) * TK + k0 + tx;
    out[obase + (size_t)(ty     ) * TK] = acc0 + bias;
    out[obase + (size_t)(ty +  8) * TK] = acc1 + bias;
    out[obase + (size_t)(ty + 16) * TK] = acc2 + bias;
    out[obase + (size_t)(ty + 24) * TK] = acc3 + bias;
}

extern "C" void kernel_launch(void* const* d_in, const int* in_sizes, int n_in,
                              void* d_out, int out_size)
{
    const float* query  = (const float*)d_in[0];
    const float* key    = (const float*)d_in[1];
    const float* Wq     = (const float*)d_in[2];
    const float* Wk     = (const float*)d_in[3];
    const float* w_attn = (const float*)d_in[4];
    const float* b_attn = (const float*)d_in[5];
    float* out = (float*)d_out;

    cudaFuncSetAttribute(proj_mma_kernel,
                         cudaFuncAttributeMaxDynamicSharedMemorySize, DYN_SMEM);

    dim3 tg(QD / 32, CD / 32, 2);              // (32, 8, 2)
    transpose_w<<<tg, 256>>>(Wq, Wk);

    dim3 pg((B_ * TQ) / BM, CD / BN, 2);       // (16, 4, 2) = 128 CTAs
    proj_mma_kernel<<<pg, 256, DYN_SMEM>>>(query, key);

    dim3 sg(TK / 32, TQ / 32, B_);             // (16, 16, 4)
    score_kernel<<<sg, 256>>>(w_attn, b_attn, out);
}

// round 5
// speedup vs baseline: 1.5248x; 1.0034x over previous
#include <cuda_runtime.h>
#include <cuda_fp16.h>
#include <cstdint>

#define B_  4
#define TQ  512
#define TK  512
#define QD  1024
#define CD  256

// Scratch: projected tensors TRANSPOSED [b][c][row] (C-major), plus W^T copies.
__device__ float g_q2t[B_ * CD * TQ];
__device__ float g_k2t[B_ * CD * TK];
__device__ float g_wqt[CD * QD];     // Wq^T: [n][k], pre-rounded to tf32-RN
__device__ float g_wkt[CD * QD];

__device__ __forceinline__ uint32_t smem_u32(const void* p) {
    uint32_t a;
    asm("{ .reg .u64 t; cvta.to.shared.u64 t, %1; cvt.u32.u64 %0, t; }"
        : "=r"(a) : "l"(p));
    return a;
}
__device__ __forceinline__ void cp_async16(uint32_t saddr, const void* g) {
    asm volatile("cp.async.cg.shared.global [%0], [%1], 16;" :: "r"(saddr), "l"(g));
}
__device__ __forceinline__ void cp_commit() {
    asm volatile("cp.async.commit_group;" ::: "memory");
}
__device__ __forceinline__ void cp_wait1() {
    asm volatile("cp.async.wait_group 1;" ::: "memory");
}
__device__ __forceinline__ void cp_wait0() {
    asm volatile("cp.async.wait_group 0;" ::: "memory");
}
__device__ __forceinline__ void mma_tf32(float* d, const uint32_t* a, const uint32_t* b) {
    asm volatile(
        "mma.sync.aligned.m16n8k8.row.col.f32.tf32.tf32.f32 "
        "{%0,%1,%2,%3}, {%4,%5,%6,%7}, {%8,%9}, {%0,%1,%2,%3};\n"
        : "+f"(d[0]), "+f"(d[1]), "+f"(d[2]), "+f"(d[3])
        : "r"(a[0]), "r"(a[1]), "r"(a[2]), "r"(a[3]), "r"(b[0]), "r"(b[1]));
}
__device__ __forceinline__ __half2 tanh_h2(__half2 x) {
    uint32_t y, xi = *(uint32_t*)&x;
    asm("tanh.approx.f16x2 %0, %1;" : "=r"(y) : "r"(xi));
    return *(__half2*)&y;
}
// Round fp32 bit pattern so tf32 truncation (drop 13 bits) becomes round-to-nearest.
#define TF32_RN(u) ((u) + 0x1000u)

// ---------------------------------------------------------------------------
// Transpose W [K=1024, N=256] -> Wt [N=256, K=1024], pre-rounded to tf32-RN.
// ---------------------------------------------------------------------------
__global__ __launch_bounds__(256) void transpose_w(
    const float* __restrict__ Wq, const float* __restrict__ Wk)
{
    __shared__ float tile[32][33];
    const float* W  = blockIdx.z ? Wk : Wq;
    float*       Wt = blockIdx.z ? g_wkt : g_wqt;
    const int k0 = blockIdx.x * 32;
    const int n0 = blockIdx.y * 32;
    const int tx = threadIdx.x & 31, ty = threadIdx.x >> 5;  // 32 x 8
    #pragma unroll
    for (int r = 0; r < 32; r += 8) {
        uint32_t u = __float_as_uint(W[(size_t)(k0 + ty + r) * CD + n0 + tx]);
        tile[ty + r][tx] = __uint_as_float(TF32_RN(u));
    }
    __syncthreads();
    #pragma unroll
    for (int r = 0; r < 32; r += 8)
        Wt[(size_t)(n0 + ty + r) * QD + k0 + tx] = tile[tx][ty + r];
}

// ---------------------------------------------------------------------------
// Projection via mma.sync tf32. 3-stage cp.async pipeline, 1 sync/iter.
// ---------------------------------------------------------------------------
#define BM     128
#define BN     64
#define BK     32
#define LDS_S  36
#define A_FL   (BM * LDS_S)
#define B_FL   (BN * LDS_S)
#define NITER  (QD / BK)
#define STG_LD 132
#define STAGES 3
#define DYN_SMEM (STAGES * (A_FL + B_FL) * 4)   // 82944 B

__global__ __launch_bounds__(256) void proj_mma_kernel(
    const float* __restrict__ Xq, const float* __restrict__ Xk)
{
    extern __shared__ float sm[];
    const uint32_t smb = smem_u32(sm);

    float*   Abuf[STAGES];
    float*   Bbuf[STAGES];
    uint32_t a_u[STAGES], b_u[STAGES];
    #pragma unroll
    for (int s = 0; s < STAGES; s++) {
        Abuf[s] = sm + s * (A_FL + B_FL);
        Bbuf[s] = Abuf[s] + A_FL;
        a_u[s]  = smb + (uint32_t)(s * (A_FL + B_FL)) * 4u;
        b_u[s]  = a_u[s] + A_FL * 4u;
    }

    const int t    = threadIdx.x;
    const int lane = t & 31;
    const int wid  = t >> 5;
    const int wm   = wid & 3;
    const int wn   = wid >> 2;
    const int r    = lane >> 2;
    const int c    = lane & 3;

    const float* X    = blockIdx.z ? Xk : Xq;
    const float* Wt   = blockIdx.z ? g_wkt : g_wqt;
    float*       OutT = blockIdx.z ? g_k2t : g_q2t;

    const int m0 = blockIdx.x * BM;
    const int n0 = blockIdx.y * BN;

    const float* Xb = X  + (size_t)m0 * QD;
    const float* Wb = Wt + (size_t)n0 * QD;

    const int arow = t >> 3;
    const int aj   = t & 7;

    float acc[2][4][4] = {};

    #pragma unroll
    for (int p = 0; p < 2; p++) {
        const int kf = p * BK;
        #pragma unroll
        for (int it = 0; it < 4; it++) {
            const int row = arow + it * 32;
            cp_async16(a_u[p] + (uint32_t)(row * LDS_S + aj * 4) * 4,
                       Xb + (size_t)row * QD + kf + aj * 4);
        }
        #pragma unroll
        for (int it = 0; it < 2; it++) {
            const int row = arow + it * 32;
            cp_async16(b_u[p] + (uint32_t)(row * LDS_S + aj * 4) * 4,
                       Wb + (size_t)row * QD + kf + aj * 4);
        }
        cp_commit();
    }

    for (int i = 0; i < NITER; i++) {
        if (i + 1 < NITER) cp_wait1(); else cp_wait0();
        __syncthreads();

        const int sb = i % STAGES;
        const float* As = Abuf[sb];
        const float* Bs = Bbuf[sb];

        #pragma unroll
        for (int kfi = 0; kfi < 4; kfi++) {
            const int kf = kfi * 8;
            uint32_t af[2][4], bf[4][2];
            #pragma unroll
            for (int mt = 0; mt < 2; mt++) {
                const int m = wm * 32 + mt * 16 + r;
                af[mt][0] = TF32_RN(__float_as_uint(As[(m    ) * LDS_S + kf + c    ]));
                af[mt][1] = TF32_RN(__float_as_uint(As[(m + 8) * LDS_S + kf + c    ]));
                af[mt][2] = TF32_RN(__float_as_uint(As[(m    ) * LDS_S + kf + c + 4]));
                af[mt][3] = TF32_RN(__float_as_uint(As[(m + 8) * LDS_S + kf + c + 4]));
            }
            #pragma unroll
            for (int nt = 0; nt < 4; nt++) {
                const int n = wn * 32 + nt * 8 + r;
                bf[nt][0] = __float_as_uint(Bs[n * LDS_S + kf + c    ]);
                bf[nt][1] = __float_as_uint(Bs[n * LDS_S + kf + c + 4]);
            }
            #pragma unroll
            for (int mt = 0; mt < 2; mt++)
                #pragma unroll
                for (int nt = 0; nt < 4; nt++)
                    mma_tf32(acc[mt][nt], af[mt], bf[nt]);
        }

        if (i + 2 < NITER) {
            const int nb = (i + 2) % STAGES;
            const int kf = (i + 2) * BK;
            #pragma unroll
            for (int it = 0; it < 4; it++) {
                const int row = arow + it * 32;
                cp_async16(a_u[nb] + (uint32_t)(row * LDS_S + aj * 4) * 4,
                           Xb + (size_t)row * QD + kf + aj * 4);
            }
            #pragma unroll
            for (int it = 0; it < 2; it++) {
                const int row = arow + it * 32;
                cp_async16(b_u[nb] + (uint32_t)(row * LDS_S + aj * 4) * 4,
                           Wb + (size_t)row * QD + kf + aj * 4);
            }
        }
        cp_commit();
    }

    __syncthreads();

    float* stg = sm;
    #pragma unroll
    for (int mt = 0; mt < 2; mt++) {
        const int mlo = wm * 32 + mt * 16 + r;
        #pragma unroll
        for (int nt = 0; nt < 4; nt++) {
            const int n = wn * 32 + nt * 8 + 2 * c;
            stg[(n    ) * STG_LD + mlo    ] = acc[mt][nt][0];
            stg[(n + 1) * STG_LD + mlo    ] = acc[mt][nt][1];
            stg[(n    ) * STG_LD + mlo + 8] = acc[mt][nt][2];
            stg[(n + 1) * STG_LD + mlo + 8] = acc[mt][nt][3];
        }
    }
    __syncthreads();

    const int b_idx = m0 >> 9;
    const int m_ib  = m0 & 511;
    #pragma unroll
    for (int it = 0; it < 8; it++) {
        const int idx = t + it * 256;
        const int n   = idx >> 5;
        const int mj  = idx & 31;
        float4 v = *(const float4*)&stg[n * STG_LD + mj * 4];
        *(float4*)&OutT[((size_t)b_idx * CD + n0 + n) * TQ + m_ib + mj * 4] = v;
    }
}

// ---------------------------------------------------------------------------
// Score kernel: f16x2 tanh with HALF2 accumulation (HFMA2), fp32 flush every
// 8 channel-pairs. No conversions in the hot loop.
// out[b,q,k] = b + sum_c w[c]*tanh(q2[b,q,c]+k2[b,k,c])
// ---------------------------------------------------------------------------
__global__ __launch_bounds__(256) void score_kernel(
    const float* __restrict__ w_attn, const float* __restrict__ b_attn,
    float* __restrict__ out)
{
    const int b  = blockIdx.z;
    const int q0 = blockIdx.y * 32;
    const int k0 = blockIdx.x * 32;

    __shared__ __half2 q_s2[32][32];   // [cpair][q col]
    __shared__ __half2 k_s2[32][32];   // [cpair][k col]
    __shared__ __half2 w_s2[CD / 2];   // packed (w[2c], w[2c+1])

    const int t  = threadIdx.x;
    const int ty = t >> 5;    // 0..7
    const int tx = t & 31;    // 0..31

    if (t < CD / 2) {
        float2 wv = *(const float2*)&w_attn[2 * t];
        w_s2[t] = __floats2half2_rn(wv.x, wv.y);
    }

    const float* qbase = g_q2t + (size_t)b * CD * TQ + q0;
    const float* kbase = g_k2t + (size_t)b * CD * TK + k0;

    float acc0 = 0.f, acc1 = 0.f, acc2 = 0.f, acc3 = 0.f;

    for (int c0 = 0; c0 < CD; c0 += 64) {
        __syncthreads();
        {   // load + convert: thread -> (cpair, 4 cols) for q and k
            const int cp   = t >> 3;          // 0..31
            const int col4 = (t & 7) << 2;    // 0..28
            const size_t r0 = (size_t)(c0 + 2 * cp) * TQ + col4;
            float4 a0 = *(const float4*)&qbase[r0];
            float4 a1 = *(const float4*)&qbase[r0 + TQ];
            q_s2[cp][col4 + 0] = __floats2half2_rn(a0.x, a1.x);
            q_s2[cp][col4 + 1] = __floats2half2_rn(a0.y, a1.y);
            q_s2[cp][col4 + 2] = __floats2half2_rn(a0.z, a1.z);
            q_s2[cp][col4 + 3] = __floats2half2_rn(a0.w, a1.w);
            float4 c4 = *(const float4*)&kbase[r0];
            float4 c5 = *(const float4*)&kbase[r0 + TK];
            k_s2[cp][col4 + 0] = __floats2half2_rn(c4.x, c5.x);
            k_s2[cp][col4 + 1] = __floats2half2_rn(c4.y, c5.y);
            k_s2[cp][col4 + 2] = __floats2half2_rn(c4.z, c5.z);
            k_s2[cp][col4 + 3] = __floats2half2_rn(c4.w, c5.w);
        }
        __syncthreads();

        #pragma unroll
        for (int ch = 0; ch < 4; ch++) {         // 4 chunks of 8 cpairs
            __half2 h0 = __half2half2(__ushort_as_half(0));
            __half2 h1 = h0, h2 = h0, h3 = h0;
            #pragma unroll
            for (int j = 0; j < 8; j++) {
                const int cp = ch * 8 + j;
                const __half2 kh = k_s2[cp][tx];
                const __half2 w2 = w_s2[(c0 >> 1) + cp];
                h0 = __hfma2(w2, tanh_h2(__hadd2(q_s2[cp][ty     ], kh)), h0);
                h1 = __hfma2(w2, tanh_h2(__hadd2(q_s2[cp][ty +  8], kh)), h1);
                h2 = __hfma2(w2, tanh_h2(__hadd2(q_s2[cp][ty + 16], kh)), h2);
                h3 = __hfma2(w2, tanh_h2(__hadd2(q_s2[cp][ty + 24], kh)), h3);
            }
            float2 f0 = __half22float2(h0); acc0 += f0.x + f0.y;
            float2 f1 = __half22float2(h1); acc1 += f1.x + f1.y;
            float2 f2 = __half22float2(h2); acc2 += f2.x + f2.y;
            float2 f3 = __half22float2(h3); acc3 += f3.x + f3.y;
        }
    }

    const float bias = b_attn[0];
    const size_t obase = ((size_t)b * TQ + q0) * TK + k0 + tx;
    out[obase + (size_t)(ty     ) * TK] = acc0 + bias;
    out[obase + (size_t)(ty +  8) * TK] = acc1 + bias;
    out[obase + (size_t)(ty + 16) * TK] = acc2 + bias;
    out[obase + (size_t)(ty + 24) * TK] = acc3 + bias;
}

extern "C" void kernel_launch(void* const* d_in, const int* in_sizes, int n_in,
                              void* d_out, int out_size)
{
    const float* query  = (const float*)d_in[0];
    const float* key    = (const float*)d_in[1];
    const float* Wq     = (const float*)d_in[2];
    const float* Wk     = (const float*)d_in[3];
    const float* w_attn = (const float*)d_in[4];
    const float* b_attn = (const float*)d_in[5];
    float* out = (float*)d_out;

    cudaFuncSetAttribute(proj_mma_kernel,
                         cudaFuncAttributeMaxDynamicSharedMemorySize, DYN_SMEM);

    dim3 tg(QD / 32, CD / 32, 2);              // (32, 8, 2)
    transpose_w<<<tg, 256>>>(Wq, Wk);

    dim3 pg((B_ * TQ) / BM, CD / BN, 2);       // (16, 4, 2) = 128 CTAs
    proj_mma_kernel<<<pg, 256, DYN_SMEM>>>(query, key);

    dim3 sg(TK / 32, TQ / 32, B_);             // (16, 16, 4)
    score_kernel<<<sg, 256>>>(w_attn, b_attn, out);
}

// round 6
// speedup vs baseline: 1.5527x; 1.0183x over previous
#include <cuda_runtime.h>
#include <cstdint>

#define B_  4
#define TQ  512
#define TK  512
#define QD  1024
#define CD  256

// Scratch: projected tensors TRANSPOSED [b][c][row] (C-major), plus W^T copies.
__device__ float g_q2t[B_ * CD * TQ];
__device__ float g_k2t[B_ * CD * TK];
__device__ float g_wqt[CD * QD];     // Wq^T: [n][k], pre-rounded to tf32-RN
__device__ float g_wkt[CD * QD];

__device__ __forceinline__ uint32_t smem_u32(const void* p) {
    uint32_t a;
    asm("{ .reg .u64 t; cvta.to.shared.u64 t, %1; cvt.u32.u64 %0, t; }"
        : "=r"(a) : "l"(p));
    return a;
}
__device__ __forceinline__ void cp_async16(uint32_t saddr, const void* g) {
    asm volatile("cp.async.cg.shared.global [%0], [%1], 16;" :: "r"(saddr), "l"(g));
}
__device__ __forceinline__ void cp_commit() {
    asm volatile("cp.async.commit_group;" ::: "memory");
}
__device__ __forceinline__ void cp_wait1() {
    asm volatile("cp.async.wait_group 1;" ::: "memory");
}
__device__ __forceinline__ void cp_wait0() {
    asm volatile("cp.async.wait_group 0;" ::: "memory");
}
__device__ __forceinline__ void mma_tf32(float* d, const uint32_t* a, const uint32_t* b) {
    asm volatile(
        "mma.sync.aligned.m16n8k8.row.col.f32.tf32.tf32.f32 "
        "{%0,%1,%2,%3}, {%4,%5,%6,%7}, {%8,%9}, {%0,%1,%2,%3};\n"
        : "+f"(d[0]), "+f"(d[1]), "+f"(d[2]), "+f"(d[3])
        : "r"(a[0]), "r"(a[1]), "r"(a[2]), "r"(a[3]), "r"(b[0]), "r"(b[1]));
}
__device__ __forceinline__ float tanh_fast(float x) {
    float y;
    asm("tanh.approx.f32 %0, %1;" : "=f"(y) : "f"(x));
    return y;
}
// Round fp32 bit pattern so tf32 truncation (drop 13 bits) becomes round-to-nearest.
#define TF32_RN(u) ((u) + 0x1000u)

// ---------------------------------------------------------------------------
// Transpose W [K=1024, N=256] -> Wt [N=256, K=1024], pre-rounded to tf32-RN.
// ---------------------------------------------------------------------------
__global__ __launch_bounds__(256) void transpose_w(
    const float* __restrict__ Wq, const float* __restrict__ Wk)
{
    __shared__ float tile[32][33];
    const float* W  = blockIdx.z ? Wk : Wq;
    float*       Wt = blockIdx.z ? g_wkt : g_wqt;
    const int k0 = blockIdx.x * 32;
    const int n0 = blockIdx.y * 32;
    const int tx = threadIdx.x & 31, ty = threadIdx.x >> 5;  // 32 x 8
    #pragma unroll
    for (int r = 0; r < 32; r += 8) {
        uint32_t u = __float_as_uint(W[(size_t)(k0 + ty + r) * CD + n0 + tx]);
        tile[ty + r][tx] = __uint_as_float(TF32_RN(u));
    }
    __syncthreads();
    #pragma unroll
    for (int r = 0; r < 32; r += 8)
        Wt[(size_t)(n0 + ty + r) * QD + k0 + tx] = tile[tx][ty + r];
}

// ---------------------------------------------------------------------------
// Projection via mma.sync tf32. BK=64, 3-stage cp.async pipeline, 1 sync/iter.
// C[m][n] = sum_k X[m][k]*Wt[n][k]; output stored C-major transposed.
// 8 warps = 4(M) x 2(N), warp tile 32x32, 16 K-iterations (barriers halved).
// ---------------------------------------------------------------------------
#define BM     128
#define BN     64
#define BK     64
#define LDS_S  68                        // 64 + 4: fragment banks (4r+c)%32 distinct
#define A_FL   (BM * LDS_S)              // 8704 floats
#define B_FL   (BN * LDS_S)              // 4352 floats
#define NITER  (QD / BK)                 // 16
#define STG_LD 132
#define STAGES 3
#define DYN_SMEM (STAGES * (A_FL + B_FL) * 4)   // 156672 B

__global__ __launch_bounds__(256) void proj_mma_kernel(
    const float* __restrict__ Xq, const float* __restrict__ Xk)
{
    extern __shared__ float sm[];
    const uint32_t smb = smem_u32(sm);

    float*   Abuf[STAGES];
    float*   Bbuf[STAGES];
    uint32_t a_u[STAGES], b_u[STAGES];
    #pragma unroll
    for (int s = 0; s < STAGES; s++) {
        Abuf[s] = sm + s * (A_FL + B_FL);
        Bbuf[s] = Abuf[s] + A_FL;
        a_u[s]  = smb + (uint32_t)(s * (A_FL + B_FL)) * 4u;
        b_u[s]  = a_u[s] + A_FL * 4u;
    }

    const int t    = threadIdx.x;
    const int lane = t & 31;
    const int wid  = t >> 5;
    const int wm   = wid & 3;
    const int wn   = wid >> 2;
    const int r    = lane >> 2;
    const int c    = lane & 3;

    const float* X    = blockIdx.z ? Xk : Xq;
    const float* Wt   = blockIdx.z ? g_wkt : g_wqt;
    float*       OutT = blockIdx.z ? g_k2t : g_q2t;

    const int m0 = blockIdx.x * BM;
    const int n0 = blockIdx.y * BN;

    const float* Xb = X  + (size_t)m0 * QD;
    const float* Wb = Wt + (size_t)n0 * QD;

    // cp.async mapping: 16B chunks; 64-float rows = 16 chunks/row.
    const int arow = t >> 4;             // 0..15 (+16 per it)
    const int aj   = t & 15;             // chunk within row

    float acc[2][4][4] = {};

    // ---- prologue: tiles 0 and 1 ----
    #pragma unroll
    for (int p = 0; p < 2; p++) {
        const int kf = p * BK;
        #pragma unroll
        for (int it = 0; it < 8; it++) {         // A: 128 rows
            const int row = arow + it * 16;
            cp_async16(a_u[p] + (uint32_t)(row * LDS_S + aj * 4) * 4,
                       Xb + (size_t)row * QD + kf + aj * 4);
        }
        #pragma unroll
        for (int it = 0; it < 4; it++) {         // B: 64 rows
            const int row = arow + it * 16;
            cp_async16(b_u[p] + (uint32_t)(row * LDS_S + aj * 4) * 4,
                       Wb + (size_t)row * QD + kf + aj * 4);
        }
        cp_commit();
    }

    for (int i = 0; i < NITER; i++) {
        if (i + 1 < NITER) cp_wait1(); else cp_wait0();
        __syncthreads();

        const int sb = i % STAGES;
        const float* As = Abuf[sb];
        const float* Bs = Bbuf[sb];

        #pragma unroll
        for (int kfi = 0; kfi < 8; kfi++) {
            const int kf = kfi * 8;
            uint32_t af[2][4], bf[4][2];
            #pragma unroll
            for (int mt = 0; mt < 2; mt++) {
                const int m = wm * 32 + mt * 16 + r;
                af[mt][0] = TF32_RN(__float_as_uint(As[(m    ) * LDS_S + kf + c    ]));
                af[mt][1] = TF32_RN(__float_as_uint(As[(m + 8) * LDS_S + kf + c    ]));
                af[mt][2] = TF32_RN(__float_as_uint(As[(m    ) * LDS_S + kf + c + 4]));
                af[mt][3] = TF32_RN(__float_as_uint(As[(m + 8) * LDS_S + kf + c + 4]));
            }
            #pragma unroll
            for (int nt = 0; nt < 4; nt++) {
                const int n = wn * 32 + nt * 8 + r;
                bf[nt][0] = __float_as_uint(Bs[n * LDS_S + kf + c    ]);
                bf[nt][1] = __float_as_uint(Bs[n * LDS_S + kf + c + 4]);
            }
            #pragma unroll
            for (int mt = 0; mt < 2; mt++)
                #pragma unroll
                for (int nt = 0; nt < 4; nt++)
                    mma_tf32(acc[mt][nt], af[mt], bf[nt]);
        }

        // prefetch tile i+2 into stage (i+2)%STAGES
        if (i + 2 < NITER) {
            const int nb = (i + 2) % STAGES;
            const int kf = (i + 2) * BK;
            #pragma unroll
            for (int it = 0; it < 8; it++) {
                const int row = arow + it * 16;
                cp_async16(a_u[nb] + (uint32_t)(row * LDS_S + aj * 4) * 4,
                           Xb + (size_t)row * QD + kf + aj * 4);
            }
            #pragma unroll
            for (int it = 0; it < 4; it++) {
                const int row = arow + it * 16;
                cp_async16(b_u[nb] + (uint32_t)(row * LDS_S + aj * 4) * 4,
                           Wb + (size_t)row * QD + kf + aj * 4);
            }
        }
        cp_commit();
    }

    __syncthreads();

    // ---- epilogue: stage transposed [n][m], store C-major float4 ----
    float* stg = sm;                     // 64*132 = 8448 floats, fits
    #pragma unroll
    for (int mt = 0; mt < 2; mt++) {
        const int mlo = wm * 32 + mt * 16 + r;
        #pragma unroll
        for (int nt = 0; nt < 4; nt++) {
            const int n = wn * 32 + nt * 8 + 2 * c;
            stg[(n    ) * STG_LD + mlo    ] = acc[mt][nt][0];
            stg[(n + 1) * STG_LD + mlo    ] = acc[mt][nt][1];
            stg[(n    ) * STG_LD + mlo + 8] = acc[mt][nt][2];
            stg[(n + 1) * STG_LD + mlo + 8] = acc[mt][nt][3];
        }
    }
    __syncthreads();

    const int b_idx = m0 >> 9;
    const int m_ib  = m0 & 511;
    #pragma unroll
    for (int it = 0; it < 8; it++) {
        const int idx = t + it * 256;
        const int n   = idx >> 5;
        const int mj  = idx & 31;
        float4 v = *(const float4*)&stg[n * STG_LD + mj * 4];
        *(float4*)&OutT[((size_t)b_idx * CD + n0 + n) * TQ + m_ib + mj * 4] = v;
    }
}

// ---------------------------------------------------------------------------
// Score kernel (R3 fp32 version): MUFU-bound tanh core at the HW floor.
// out[b,q,k] = b + sum_c w[c]*tanh(q2[b,q,c]+k2[b,k,c])
// ---------------------------------------------------------------------------
__global__ __launch_bounds__(256) void score_kernel(
    const float* __restrict__ w_attn, const float* __restrict__ b_attn,
    float* __restrict__ out)
{
    const int b  = blockIdx.z;
    const int q0 = blockIdx.y * 32;
    const int k0 = blockIdx.x * 32;

    __shared__ float q_s[64][32];
    __shared__ float k_s[64][32];
    __shared__ float w_s[CD];

    const int t  = threadIdx.x;
    const int ty = t >> 5;
    const int tx = t & 31;

    w_s[t] = w_attn[t];

    const float* qbase = g_q2t + (size_t)b * CD * TQ + q0;
    const float* kbase = g_k2t + (size_t)b * CD * TK + k0;

    float acc0 = 0.f, acc1 = 0.f, acc2 = 0.f, acc3 = 0.f;

    for (int c0 = 0; c0 < CD; c0 += 64) {
        __syncthreads();
        #pragma unroll
        for (int rr = 0; rr < 2; rr++) {
            const int v    = t + rr * 256;
            const int row  = v >> 3;
            const int col4 = (v & 7) << 2;
            *(float4*)&q_s[row][col4] =
                *(const float4*)&qbase[(size_t)(c0 + row) * TQ + col4];
            *(float4*)&k_s[row][col4] =
                *(const float4*)&kbase[(size_t)(c0 + row) * TK + col4];
        }
        __syncthreads();

        #pragma unroll 8
        for (int cc = 0; cc < 64; cc++) {
            const float kv = k_s[cc][tx];
            const float w  = w_s[c0 + cc];
            acc0 += w * tanh_fast(q_s[cc][ty     ] + kv);
            acc1 += w * tanh_fast(q_s[cc][ty +  8] + kv);
            acc2 += w * tanh_fast(q_s[cc][ty + 16] + kv);
            acc3 += w * tanh_fast(q_s[cc][ty + 24] + kv);
        }
    }

    const float bias = b_attn[0];
    const size_t obase = ((size_t)b * TQ + q0) * TK + k0 + tx;
    out[obase + (size_t)(ty     ) * TK] = acc0 + bias;
    out[obase + (size_t)(ty +  8) * TK] = acc1 + bias;
    out[obase + (size_t)(ty + 16) * TK] = acc2 + bias;
    out[obase + (size_t)(ty + 24) * TK] = acc3 + bias;
}

extern "C" void kernel_launch(void* const* d_in, const int* in_sizes, int n_in,
                              void* d_out, int out_size)
{
    const float* query  = (const float*)d_in[0];
    const float* key    = (const float*)d_in[1];
    const float* Wq     = (const float*)d_in[2];
    const float* Wk     = (const float*)d_in[3];
    const float* w_attn = (const float*)d_in[4];
    const float* b_attn = (const float*)d_in[5];
    float* out = (float*)d_out;

    cudaFuncSetAttribute(proj_mma_kernel,
                         cudaFuncAttributeMaxDynamicSharedMemorySize, DYN_SMEM);

    dim3 tg(QD / 32, CD / 32, 2);              // (32, 8, 2)
    transpose_w<<<tg, 256>>>(Wq, Wk);

    dim3 pg((B_ * TQ) / BM, CD / BN, 2);       // (16, 4, 2) = 128 CTAs
    proj_mma_kernel<<<pg, 256, DYN_SMEM>>>(query, key);

    dim3 sg(TK / 32, TQ / 32, B_);             // (16, 16, 4)
    score_kernel<<<sg, 256>>>(w_attn, b_attn, out);
}

// round 7
// speedup vs baseline: 1.5833x; 1.0197x over previous
#include <cuda_runtime.h>
#include <cstdint>

#define B_  4
#define TQ  512
#define TK  512
#define QD  1024
#define CD  256

// Scratch: projected tensors TRANSPOSED [b][c][row] (C-major).
__device__ float g_q2t[B_ * CD * TQ];
__device__ float g_k2t[B_ * CD * TK];

__device__ __forceinline__ uint32_t smem_u32(const void* p) {
    uint32_t a;
    asm("{ .reg .u64 t; cvta.to.shared.u64 t, %1; cvt.u32.u64 %0, t; }"
        : "=r"(a) : "l"(p));
    return a;
}
__device__ __forceinline__ void cp_async16(uint32_t saddr, const void* g) {
    asm volatile("cp.async.cg.shared.global [%0], [%1], 16;" :: "r"(saddr), "l"(g));
}
__device__ __forceinline__ void cp_commit() {
    asm volatile("cp.async.commit_group;" ::: "memory");
}
__device__ __forceinline__ void cp_wait1() {
    asm volatile("cp.async.wait_group 1;" ::: "memory");
}
__device__ __forceinline__ void cp_wait0() {
    asm volatile("cp.async.wait_group 0;" ::: "memory");
}
__device__ __forceinline__ void mma_tf32(float* d, const uint32_t* a, const uint32_t* b) {
    asm volatile(
        "mma.sync.aligned.m16n8k8.row.col.f32.tf32.tf32.f32 "
        "{%0,%1,%2,%3}, {%4,%5,%6,%7}, {%8,%9}, {%0,%1,%2,%3};\n"
        : "+f"(d[0]), "+f"(d[1]), "+f"(d[2]), "+f"(d[3])
        : "r"(a[0]), "r"(a[1]), "r"(a[2]), "r"(a[3]), "r"(b[0]), "r"(b[1]));
}
__device__ __forceinline__ float tanh_fast(float x) {
    float y;
    asm("tanh.approx.f32 %0, %1;" : "=f"(y) : "f"(x));
    return y;
}
// Round fp32 bit pattern so tf32 truncation (drop 13 bits) becomes round-to-nearest.
#define TF32_RN(u) ((u) + 0x1000u)

// ---------------------------------------------------------------------------
// Projection via mma.sync tf32, no W pre-transpose.
// C[m][n] = sum_k X[m][k]*W[k][n]; output stored C-major transposed.
// A smem: [m][k] stride 68 (row-major K). B smem: NATURAL W layout [k][n],
// stride 72 -> fragment banks (8c + n) mod 32 all distinct.
// 8 warps = 4(M) x 2(N), warp tile 32x32, BK=64, 3-stage cp.async, 1 sync/iter.
// ---------------------------------------------------------------------------
#define BM     128
#define BN     64
#define BK     64
#define LDS_A  68                        // A stride: banks (4r+c)%32 distinct
#define LDS_B  72                        // B stride: 72%32=8 -> (8c+n)%32 distinct
#define A_FL   (BM * LDS_A)              // 8704 floats
#define B_FL   (BK * LDS_B)              // 4608 floats
#define NITER  (QD / BK)                 // 16
#define STG_LD 132
#define STAGES 3
#define DYN_SMEM (STAGES * (A_FL + B_FL) * 4)   // 159744 B

__global__ __launch_bounds__(256) void proj_mma_kernel(
    const float* __restrict__ Xq, const float* __restrict__ Xk,
    const float* __restrict__ Wq, const float* __restrict__ Wk)
{
    extern __shared__ float sm[];
    const uint32_t smb = smem_u32(sm);

    float*   Abuf[STAGES];
    float*   Bbuf[STAGES];
    uint32_t a_u[STAGES], b_u[STAGES];
    #pragma unroll
    for (int s = 0; s < STAGES; s++) {
        Abuf[s] = sm + s * (A_FL + B_FL);
        Bbuf[s] = Abuf[s] + A_FL;
        a_u[s]  = smb + (uint32_t)(s * (A_FL + B_FL)) * 4u;
        b_u[s]  = a_u[s] + A_FL * 4u;
    }

    const int t    = threadIdx.x;
    const int lane = t & 31;
    const int wid  = t >> 5;
    const int wm   = wid & 3;
    const int wn   = wid >> 2;
    const int r    = lane >> 2;
    const int c    = lane & 3;

    const float* X    = blockIdx.z ? Xk : Xq;
    const float* W    = blockIdx.z ? Wk : Wq;
    float*       OutT = blockIdx.z ? g_k2t : g_q2t;

    const int m0 = blockIdx.x * BM;
    const int n0 = blockIdx.y * BN;

    const float* Xb = X + (size_t)m0 * QD;
    const float* Wb = W + n0;                    // W[k][n0 + ...]

    // cp.async mapping (64-float rows = 16 chunks of 16B):
    const int arow = t >> 4;             // 0..15 (+16 per it)
    const int aj   = t & 15;             // chunk within row

    float acc[2][4][4] = {};

    // ---- prologue: tiles 0 and 1 ----
    #pragma unroll
    for (int p = 0; p < 2; p++) {
        const int kf = p * BK;
        #pragma unroll
        for (int it = 0; it < 8; it++) {         // A: 128 rows x 64 k
            const int row = arow + it * 16;
            cp_async16(a_u[p] + (uint32_t)(row * LDS_A + aj * 4) * 4,
                       Xb + (size_t)row * QD + kf + aj * 4);
        }
        #pragma unroll
        for (int it = 0; it < 4; it++) {         // B: 64 k-rows x 64 n (natural W)
            const int krow = arow + it * 16;
            cp_async16(b_u[p] + (uint32_t)(krow * LDS_B + aj * 4) * 4,
                       Wb + (size_t)(kf + krow) * CD + aj * 4);
        }
        cp_commit();
    }

    for (int i = 0; i < NITER; i++) {
        if (i + 1 < NITER) cp_wait1(); else cp_wait0();
        __syncthreads();

        const int sb = i % STAGES;
        const float* As = Abuf[sb];
        const float* Bs = Bbuf[sb];

        #pragma unroll
        for (int kfi = 0; kfi < 8; kfi++) {
            const int kf = kfi * 8;
            uint32_t af[2][4], bf[4][2];
            #pragma unroll
            for (int mt = 0; mt < 2; mt++) {
                const int m = wm * 32 + mt * 16 + r;
                af[mt][0] = TF32_RN(__float_as_uint(As[(m    ) * LDS_A + kf + c    ]));
                af[mt][1] = TF32_RN(__float_as_uint(As[(m + 8) * LDS_A + kf + c    ]));
                af[mt][2] = TF32_RN(__float_as_uint(As[(m    ) * LDS_A + kf + c + 4]));
                af[mt][3] = TF32_RN(__float_as_uint(As[(m + 8) * LDS_A + kf + c + 4]));
            }
            #pragma unroll
            for (int nt = 0; nt < 4; nt++) {
                const int n = wn * 32 + nt * 8 + r;
                bf[nt][0] = TF32_RN(__float_as_uint(Bs[(kf + c    ) * LDS_B + n]));
                bf[nt][1] = TF32_RN(__float_as_uint(Bs[(kf + c + 4) * LDS_B + n]));
            }
            #pragma unroll
            for (int mt = 0; mt < 2; mt++)
                #pragma unroll
                for (int nt = 0; nt < 4; nt++)
                    mma_tf32(acc[mt][nt], af[mt], bf[nt]);
        }

        // prefetch tile i+2 into stage (i+2)%STAGES
        if (i + 2 < NITER) {
            const int nb = (i + 2) % STAGES;
            const int kf = (i + 2) * BK;
            #pragma unroll
            for (int it = 0; it < 8; it++) {
                const int row = arow + it * 16;
                cp_async16(a_u[nb] + (uint32_t)(row * LDS_A + aj * 4) * 4,
                           Xb + (size_t)row * QD + kf + aj * 4);
            }
            #pragma unroll
            for (int it = 0; it < 4; it++) {
                const int krow = arow + it * 16;
                cp_async16(b_u[nb] + (uint32_t)(krow * LDS_B + aj * 4) * 4,
                           Wb + (size_t)(kf + krow) * CD + aj * 4);
            }
        }
        cp_commit();
    }

    __syncthreads();

    // ---- epilogue: stage transposed [n][m], store C-major float4 ----
    float* stg = sm;                     // 64*132 = 8448 floats, fits
    #pragma unroll
    for (int mt = 0; mt < 2; mt++) {
        const int mlo = wm * 32 + mt * 16 + r;
        #pragma unroll
        for (int nt = 0; nt < 4; nt++) {
            const int n = wn * 32 + nt * 8 + 2 * c;
            stg[(n    ) * STG_LD + mlo    ] = acc[mt][nt][0];
            stg[(n + 1) * STG_LD + mlo    ] = acc[mt][nt][1];
            stg[(n    ) * STG_LD + mlo + 8] = acc[mt][nt][2];
            stg[(n + 1) * STG_LD + mlo + 8] = acc[mt][nt][3];
        }
    }
    __syncthreads();

    const int b_idx = m0 >> 9;
    const int m_ib  = m0 & 511;
    #pragma unroll
    for (int it = 0; it < 8; it++) {
        const int idx = t + it * 256;
        const int n   = idx >> 5;
        const int mj  = idx & 31;
        float4 v = *(const float4*)&stg[n * STG_LD + mj * 4];
        *(float4*)&OutT[((size_t)b_idx * CD + n0 + n) * TQ + m_ib + mj * 4] = v;
    }
}

// ---------------------------------------------------------------------------
// Score kernel: MUFU-bound fp32 tanh core at the HW floor.
// out[b,q,k] = b + sum_c w[c]*tanh(q2[b,q,c]+k2[b,k,c])
// ---------------------------------------------------------------------------
__global__ __launch_bounds__(256) void score_kernel(
    const float* __restrict__ w_attn, const float* __restrict__ b_attn,
    float* __restrict__ out)
{
    const int b  = blockIdx.z;
    const int q0 = blockIdx.y * 32;
    const int k0 = blockIdx.x * 32;

    __shared__ float q_s[64][32];
    __shared__ float k_s[64][32];
    __shared__ float w_s[CD];

    const int t  = threadIdx.x;
    const int ty = t >> 5;
    const int tx = t & 31;

    w_s[t] = w_attn[t];

    const float* qbase = g_q2t + (size_t)b * CD * TQ + q0;
    const float* kbase = g_k2t + (size_t)b * CD * TK + k0;

    float acc0 = 0.f, acc1 = 0.f, acc2 = 0.f, acc3 = 0.f;

    for (int c0 = 0; c0 < CD; c0 += 64) {
        __syncthreads();
        #pragma unroll
        for (int rr = 0; rr < 2; rr++) {
            const int v    = t + rr * 256;
            const int row  = v >> 3;
            const int col4 = (v & 7) << 2;
            *(float4*)&q_s[row][col4] =
                *(const float4*)&qbase[(size_t)(c0 + row) * TQ + col4];
            *(float4*)&k_s[row][col4] =
                *(const float4*)&kbase[(size_t)(c0 + row) * TK + col4];
        }
        __syncthreads();

        #pragma unroll 8
        for (int cc = 0; cc < 64; cc++) {
            const float kv = k_s[cc][tx];
            const float w  = w_s[c0 + cc];
            acc0 += w * tanh_fast(q_s[cc][ty     ] + kv);
            acc1 += w * tanh_fast(q_s[cc][ty +  8] + kv);
            acc2 += w * tanh_fast(q_s[cc][ty + 16] + kv);
            acc3 += w * tanh_fast(q_s[cc][ty + 24] + kv);
        }
    }

    const float bias = b_attn[0];
    const size_t obase = ((size_t)b * TQ + q0) * TK + k0 + tx;
    out[obase + (size_t)(ty     ) * TK] = acc0 + bias;
    out[obase + (size_t)(ty +  8) * TK] = acc1 + bias;
    out[obase + (size_t)(ty + 16) * TK] = acc2 + bias;
    out[obase + (size_t)(ty + 24) * TK] = acc3 + bias;
}

extern "C" void kernel_launch(void* const* d_in, const int* in_sizes, int n_in,
                              void* d_out, int out_size)
{
    const float* query  = (const float*)d_in[0];
    const float* key    = (const float*)d_in[1];
    const float* Wq     = (const float*)d_in[2];
    const float* Wk     = (const float*)d_in[3];
    const float* w_attn = (const float*)d_in[4];
    const float* b_attn = (const float*)d_in[5];
    float* out = (float*)d_out;

    cudaFuncSetAttribute(proj_mma_kernel,
                         cudaFuncAttributeMaxDynamicSharedMemorySize, DYN_SMEM);

    dim3 pg((B_ * TQ) / BM, CD / BN, 2);       // (16, 4, 2) = 128 CTAs
    proj_mma_kernel<<<pg, 256, DYN_SMEM>>>(query, key, Wq, Wk);

    dim3 sg(TK / 32, TQ / 32, B_);             // (16, 16, 4)
    score_kernel<<<sg, 256>>>(w_attn, b_attn, out);
}